// round 5
// baseline (speedup 1.0000x reference)
#include <cuda_runtime.h>
#include <cuda_bf16.h>

// ---------------------------------------------------------------------------
// GATv2 x2, heads=1, edge_dim=1, self-loops fill='mean'.
// N=100000, E=1600000, IN=128, HID=OUT=32.
// R5: GEMM inner loop converted to packed fma.rn.f32x2 (FFMA2, 2x fp32 FMA
//     throughput; ptxas never emits it from C++). Packing along k => both
//     operands are natural 64-bit smem loads, no pack ops. Edge pass
//     unchanged from the 324us R2 design.
// ---------------------------------------------------------------------------

#define NN 100000
#define EE 1600000
#define F 32

using u64 = unsigned long long;

__device__ float g_xl[NN * F];
__device__ float g_xr[NN * F];
__device__ float g_agg[NN * F];
__device__ float g_h[NN * F];
__device__ float g_z[NN];
__device__ float g_cnt[NN];
__device__ float g_asum[NN];
__device__ float g_mean[NN];

__device__ __forceinline__ float lrelu(float v) {
    return v > 0.0f ? v : 0.2f * v;
}

// packed dual-fp32 fma: d = a*b + c  (elementwise on {lo,hi})
__device__ __forceinline__ void fma2(u64& d, u64 a, u64 b, u64 c) {
    asm("fma.rn.f32x2 %0, %1, %2, %3;" : "=l"(d) : "l"(a), "l"(b), "l"(c));
}
__device__ __forceinline__ float fold2(u64 v) {
    float lo, hi;
    asm("mov.b64 {%0, %1}, %2;" : "=f"(lo), "=f"(hi) : "l"(v));
    return lo + hi;
}

// --------------------------- small / init kernels ---------------------------

__global__ void k_zero2(float* a, float* b, int n) {
    for (int i = blockIdx.x * blockDim.x + threadIdx.x; i < n;
         i += gridDim.x * blockDim.x) { a[i] = 0.0f; b[i] = 0.0f; }
}

__global__ void k_init(float* z, float* agg, int n) {
    int tid = blockIdx.x * blockDim.x + threadIdx.x;
    int stride = gridDim.x * blockDim.x;
    for (int i = tid; i < n; i += stride) z[i] = 0.0f;
    for (int i = tid; i < n * F; i += stride) agg[i] = 0.0f;
}

__global__ void k_deg(const int* __restrict__ dst, const float* __restrict__ ea, int e) {
    int i = blockIdx.x * blockDim.x + threadIdx.x;
    if (i >= e) return;
    int d = dst[i];
    atomicAdd(&g_cnt[d], 1.0f);
    atomicAdd(&g_asum[d], ea[i]);
}

__global__ void k_mean(int n) {
    int i = blockIdx.x * blockDim.x + threadIdx.x;
    if (i >= n) return;
    g_mean[i] = g_asum[i] / fmaxf(g_cnt[i], 1.0f);
}

// ------------------------------- dense GEMM --------------------------------
// 256 threads = 8 warps; warp handles 4 nodes; lane = output column.
// W transposed+padded in shared (stride K+4, conflict-free 16B loads).
// Inner loop uses fma.rn.f32x2 with k-pair packing: accumulator holds
// {sum over even k, sum over odd k}; folded after the loop.
template <int K>
__global__ void k_gemm_lr(const float* __restrict__ x,
                          const float* __restrict__ Wl, const float* __restrict__ bl,
                          const float* __restrict__ Wr, const float* __restrict__ br,
                          float* __restrict__ xl, float* __restrict__ xr, int n) {
    constexpr int KP = K + 4;
    extern __shared__ float sm[];
    float* sWl = sm;                 // F * KP
    float* sWr = sm + F * KP;        // F * KP
    float* sx  = sm + 2 * F * KP;    // 32 * K

    for (int i = threadIdx.x; i < K * F; i += 256) {
        int k = i / F, c = i % F;
        sWl[c * KP + k] = Wl[i];
        sWr[c * KP + k] = Wr[i];
    }
    int base = blockIdx.x * 32;
    for (int i = threadIdx.x; i < 32 * K; i += 256) {
        int node = base + i / K;
        sx[i] = (node < n) ? x[node * K + (i % K)] : 0.0f;
    }
    __syncthreads();

    int lane = threadIdx.x & 31;
    int w    = threadIdx.x >> 5;

    u64 accl[4] = {0ull, 0ull, 0ull, 0ull};
    u64 accr[4] = {0ull, 0ull, 0ull, 0ull};

#pragma unroll
    for (int kk = 0; kk < K; kk += 4) {
        // 16B loads viewed as two packed f32x2 values each
        ulonglong2 wl2 = *(const ulonglong2*)&sWl[lane * KP + kk];
        ulonglong2 wr2 = *(const ulonglong2*)&sWr[lane * KP + kk];
#pragma unroll
        for (int j = 0; j < 4; j++) {
            ulonglong2 xv = *(const ulonglong2*)&sx[(w * 4 + j) * K + kk];
            fma2(accl[j], xv.x, wl2.x, accl[j]);
            fma2(accl[j], xv.y, wl2.y, accl[j]);
            fma2(accr[j], xv.x, wr2.x, accr[j]);
            fma2(accr[j], xv.y, wr2.y, accr[j]);
        }
    }

    float blv = bl[lane], brv = br[lane];
#pragma unroll
    for (int j = 0; j < 4; j++) {
        int node = base + w * 4 + j;
        if (node < n) {
            xl[node * F + lane] = fold2(accl[j]) + blv;
            xr[node * F + lane] = fold2(accr[j]) + brv;
        }
    }
}

// ---------------------------- fused edge pass ------------------------------
// 8 lanes per edge. Coalesced float4 gathers of xl[src]/xr[dst], butterfly
// score reduction over the 8-lane group, p = exp(s) (no max shift needed),
// z[dst] += p (lane 0), agg[dst] += p*xl[src] via red.global.add.v4.f32.
__global__ void k_edge(const int* __restrict__ src, const int* __restrict__ dst,
                       const float* __restrict__ ea,
                       const float* __restrict__ We, const float* __restrict__ att,
                       float* __restrict__ agg, float* __restrict__ z,
                       int e_real, int etot) {
    int t = blockIdx.x * blockDim.x + threadIdx.x;
    int e = t >> 3;
    if (e >= etot) return;
    int sub = t & 7;

    int s_i, d_i; float a;
    if (e < e_real) { s_i = src[e]; d_i = dst[e]; a = ea[e]; }
    else            { s_i = d_i = e - e_real;     a = g_mean[e - e_real]; }

    float4 u = *(const float4*)(g_xl + s_i * F + sub * 4);
    float4 v = *(const float4*)(g_xr + d_i * F + sub * 4);
    float4 w = __ldg((const float4*)We + sub);
    float4 tt = __ldg((const float4*)att + sub);

    float acc;
    acc = lrelu(u.x + v.x + a * w.x) * tt.x;
    acc = fmaf(lrelu(u.y + v.y + a * w.y), tt.y, acc);
    acc = fmaf(lrelu(u.z + v.z + a * w.z), tt.z, acc);
    acc = fmaf(lrelu(u.w + v.w + a * w.w), tt.w, acc);

    acc += __shfl_xor_sync(0xffffffffu, acc, 4);
    acc += __shfl_xor_sync(0xffffffffu, acc, 2);
    acc += __shfl_xor_sync(0xffffffffu, acc, 1);

    float p = __expf(acc);
    if (sub == 0) atomicAdd(&z[d_i], p);

    float px = p * u.x, py = p * u.y, pz = p * u.z, pw = p * u.w;
    float* o = agg + d_i * F + sub * 4;
    asm volatile("red.global.add.v4.f32 [%0], {%1,%2,%3,%4};"
                 :: "l"(o), "f"(px), "f"(py), "f"(pz), "f"(pw) : "memory");
}

// ------------------------------- epilogues ---------------------------------

__global__ void k_epi_relu(const float* __restrict__ agg, const float* __restrict__ z,
                           const float* __restrict__ b, float* __restrict__ h, int n) {
    int i = blockIdx.x * blockDim.x + threadIdx.x;
    if (i >= n * F) return;
    h[i] = fmaxf(agg[i] / z[i >> 5] + b[i & (F - 1)], 0.0f);
}

__global__ void k_epi(float* __restrict__ out, const float* __restrict__ z,
                      const float* __restrict__ b, int n) {
    int i = blockIdx.x * blockDim.x + threadIdx.x;
    if (i >= n * F) return;
    out[i] = out[i] / z[i >> 5] + b[i & (F - 1)];
}

// ---------------------------------------------------------------------------

extern "C" void kernel_launch(void* const* d_in, const int* in_sizes, int n_in,
                              void* d_out, int out_size) {
    const float* x   = (const float*)d_in[0];
    const int*   src = (const int*)d_in[1];
    const int*   dst = (const int*)d_in[2];
    const float* ea  = (const float*)d_in[3];
    const float* Wl1 = (const float*)d_in[4];
    const float* bl1 = (const float*)d_in[5];
    const float* Wr1 = (const float*)d_in[6];
    const float* br1 = (const float*)d_in[7];
    const float* We1 = (const float*)d_in[8];
    const float* at1 = (const float*)d_in[9];
    const float* b1  = (const float*)d_in[10];
    const float* Wl2 = (const float*)d_in[11];
    const float* bl2 = (const float*)d_in[12];
    const float* Wr2 = (const float*)d_in[13];
    const float* br2 = (const float*)d_in[14];
    const float* We2 = (const float*)d_in[15];
    const float* at2 = (const float*)d_in[16];
    const float* b2  = (const float*)d_in[17];

    const int n    = in_sizes[0] / 128;   // 100000
    const int e    = in_sizes[1];         // 1600000
    const int etot = e + n;

    float* out = (float*)d_out;
    float* d_xl;   cudaGetSymbolAddress((void**)&d_xl,   g_xl);
    float* d_xr;   cudaGetSymbolAddress((void**)&d_xr,   g_xr);
    float* d_agg;  cudaGetSymbolAddress((void**)&d_agg,  g_agg);
    float* d_h;    cudaGetSymbolAddress((void**)&d_h,    g_h);
    float* d_z;    cudaGetSymbolAddress((void**)&d_z,    g_z);
    float* d_cnt;  cudaGetSymbolAddress((void**)&d_cnt,  g_cnt);
    float* d_asum; cudaGetSymbolAddress((void**)&d_asum, g_asum);

    const int T = 256;
    const int gN   = (n + T - 1) / T;
    const int gNF  = (n * F + T - 1) / T;
    const int gE   = (e + T - 1) / T;
    const int gEW  = (etot * 8 + T - 1) / T;   // 8 lanes per edge
    const int gG   = (n + 31) / 32;

    const int smem128 = (2 * F * (128 + 4) + 32 * 128) * sizeof(float);  // ~50.2KB
    const int smem32  = (2 * F * (32 + 4)  + 32 * 32)  * sizeof(float);
    cudaFuncSetAttribute(k_gemm_lr<128>, cudaFuncAttributeMaxDynamicSharedMemorySize, smem128);

    // Self-loop mean edge_attr (shared by both layers)
    k_zero2<<<gN, T>>>(d_cnt, d_asum, n);
    k_deg<<<gE, T>>>(dst, ea, e);
    k_mean<<<gN, T>>>(n);

    // ---------------- Layer 1 ----------------
    k_gemm_lr<128><<<gG, T, smem128>>>(x, Wl1, bl1, Wr1, br1, d_xl, d_xr, n);
    k_init<<<gNF, T>>>(d_z, d_agg, n);
    k_edge<<<gEW, T>>>(src, dst, ea, We1, at1, d_agg, d_z, e, etot);
    k_epi_relu<<<gNF, T>>>(d_agg, d_z, b1, d_h, n);

    // ---------------- Layer 2 ----------------
    k_gemm_lr<32><<<gG, T, smem32>>>(d_h, Wl2, bl2, Wr2, br2, d_xl, d_xr, n);
    k_init<<<gNF, T>>>(d_z, out, n);
    k_edge<<<gEW, T>>>(src, dst, ea, We2, at2, out, d_z, e, etot);
    k_epi<<<gNF, T>>>(out, d_z, b2, n);
}

// round 13
// speedup vs baseline: 1.2349x; 1.2349x over previous
#include <cuda_runtime.h>
#include <cuda_bf16.h>

// ---------------------------------------------------------------------------
// GATv2 x2, heads=1, edge_dim=1, self-loops fill='mean'.
// N=100000, E=1600000, IN=128, HID=OUT=32.
// R6 (resubmit x7): persistent-block GEMM — weights loaded ONCE per block,
//     x tiles streamed with cp.async.cg into a double-buffered smem ring
//     overlapped with FFMA2 compute. Edge pass unchanged (324us design).
// ---------------------------------------------------------------------------

#define NN 100000
#define EE 1600000
#define F 32

using u64 = unsigned long long;

__device__ float g_xl[NN * F];
__device__ float g_xr[NN * F];
__device__ float g_agg[NN * F];
__device__ float g_h[NN * F];
__device__ float g_z[NN];
__device__ float g_cnt[NN];
__device__ float g_asum[NN];
__device__ float g_mean[NN];

__device__ __forceinline__ float lrelu(float v) {
    return v > 0.0f ? v : 0.2f * v;
}

// packed dual-fp32 fma: d = a*b + c  (elementwise on {lo,hi})
__device__ __forceinline__ void fma2(u64& d, u64 a, u64 b, u64 c) {
    asm("fma.rn.f32x2 %0, %1, %2, %3;" : "=l"(d) : "l"(a), "l"(b), "l"(c));
}
__device__ __forceinline__ float fold2(u64 v) {
    float lo, hi;
    asm("mov.b64 {%0, %1}, %2;" : "=f"(lo), "=f"(hi) : "l"(v));
    return lo + hi;
}

__device__ __forceinline__ unsigned smem_u32(const void* p) {
    unsigned a;
    asm("{ .reg .u64 t; cvta.to.shared.u64 t, %1; cvt.u32.u64 %0, t; }"
        : "=r"(a) : "l"(p));
    return a;
}
__device__ __forceinline__ void cp16(unsigned dst, const void* src) {
    asm volatile("cp.async.cg.shared.global [%0], [%1], 16;"
                 :: "r"(dst), "l"(src) : "memory");
}
__device__ __forceinline__ void cp_commit() {
    asm volatile("cp.async.commit_group;" ::: "memory");
}
template <int N_>
__device__ __forceinline__ void cp_wait() {
    asm volatile("cp.async.wait_group %0;" :: "n"(N_) : "memory");
}

// --------------------------- small / init kernels ---------------------------

__global__ void k_zero2(float* a, float* b, int n) {
    for (int i = blockIdx.x * blockDim.x + threadIdx.x; i < n;
         i += gridDim.x * blockDim.x) { a[i] = 0.0f; b[i] = 0.0f; }
}

__global__ void k_init(float* z, float* agg, int n) {
    int tid = blockIdx.x * blockDim.x + threadIdx.x;
    int stride = gridDim.x * blockDim.x;
    for (int i = tid; i < n; i += stride) z[i] = 0.0f;
    for (int i = tid; i < n * F; i += stride) agg[i] = 0.0f;
}

__global__ void k_deg(const int* __restrict__ dst, const float* __restrict__ ea, int e) {
    int i = blockIdx.x * blockDim.x + threadIdx.x;
    if (i >= e) return;
    int d = dst[i];
    atomicAdd(&g_cnt[d], 1.0f);
    atomicAdd(&g_asum[d], ea[i]);
}

__global__ void k_mean(int n) {
    int i = blockIdx.x * blockDim.x + threadIdx.x;
    if (i >= n) return;
    g_mean[i] = g_asum[i] / fmaxf(g_cnt[i], 1.0f);
}

// ------------------------------- dense GEMM --------------------------------
// Persistent blocks: weights loaded once, x tiles (32 nodes = contiguous
// 32*K*4 bytes) streamed via cp.async.cg into a 2-deep smem ring overlapped
// with compute. 256 threads = 8 warps; warp computes 4 nodes; lane = out col.
// NOTE: n must be a multiple of 32 (100000 = 3125*32 — holds here).
template <int K>
__global__ void k_gemm_lr(const float* __restrict__ x,
                          const float* __restrict__ Wl, const float* __restrict__ bl,
                          const float* __restrict__ Wr, const float* __restrict__ br,
                          float* __restrict__ xl, float* __restrict__ xr, int n) {
    constexpr int KP = K + 4;
    constexpr int TILE_FLOATS = 32 * K;           // floats per node tile
    constexpr int CP_PER_THREAD = TILE_FLOATS / (256 * 4);  // 16B ops per thread
    extern __shared__ float sm[];
    float* sWl = sm;                       // F * KP
    float* sWr = sm + F * KP;              // F * KP
    float* sx0 = sm + 2 * F * KP;          // TILE_FLOATS
    float* sx1 = sx0 + TILE_FLOATS;        // TILE_FLOATS

    // Load weights transposed+padded — once per block
    for (int i = threadIdx.x; i < K * F; i += 256) {
        int k = i / F, c = i % F;
        sWl[c * KP + k] = Wl[i];
        sWr[c * KP + k] = Wr[i];
    }

    const int ntiles = n >> 5;
    unsigned sx_u32[2] = { smem_u32(sx0), smem_u32(sx1) };

    // Prologue: issue first tile into buffer 0
    int tile = blockIdx.x;
    if (tile < ntiles) {
        const char* srcb = (const char*)(x + (size_t)tile * TILE_FLOATS);
#pragma unroll
        for (int j = 0; j < CP_PER_THREAD; j++) {
            int off = (threadIdx.x + j * 256) * 16;
            cp16(sx_u32[0] + off, srcb + off);
        }
    }
    cp_commit();

    int lane = threadIdx.x & 31;
    int w    = threadIdx.x >> 5;
    float blv = bl[lane], brv = br[lane];
    int buf = 0;

    for (; tile < ntiles; tile += gridDim.x) {
        // Prefetch next tile into the other buffer
        int nxt = tile + gridDim.x;
        if (nxt < ntiles) {
            const char* srcb = (const char*)(x + (size_t)nxt * TILE_FLOATS);
#pragma unroll
            for (int j = 0; j < CP_PER_THREAD; j++) {
                int off = (threadIdx.x + j * 256) * 16;
                cp16(sx_u32[buf ^ 1] + off, srcb + off);
            }
        }
        cp_commit();
        cp_wait<1>();          // current tile's group has landed
        __syncthreads();       // (also covers weight fill on first iteration)

        const float* sx = buf ? sx1 : sx0;
        u64 accl[4] = {0ull, 0ull, 0ull, 0ull};
        u64 accr[4] = {0ull, 0ull, 0ull, 0ull};
#pragma unroll
        for (int kk = 0; kk < K; kk += 4) {
            ulonglong2 wl2 = *(const ulonglong2*)&sWl[lane * KP + kk];
            ulonglong2 wr2 = *(const ulonglong2*)&sWr[lane * KP + kk];
#pragma unroll
            for (int j = 0; j < 4; j++) {
                ulonglong2 xv = *(const ulonglong2*)&sx[(w * 4 + j) * K + kk];
                fma2(accl[j], xv.x, wl2.x, accl[j]);
                fma2(accl[j], xv.y, wl2.y, accl[j]);
                fma2(accr[j], xv.x, wr2.x, accr[j]);
                fma2(accr[j], xv.y, wr2.y, accr[j]);
            }
        }
        int base = tile * 32;
#pragma unroll
        for (int j = 0; j < 4; j++) {
            int node = base + w * 4 + j;
            xl[node * F + lane] = fold2(accl[j]) + blv;
            xr[node * F + lane] = fold2(accr[j]) + brv;
        }
        __syncthreads();       // all reads of sx[buf] done before reuse
        buf ^= 1;
    }
}

// ---------------------------- fused edge pass ------------------------------
// 8 lanes per edge. Coalesced float4 gathers of xl[src]/xr[dst], butterfly
// score reduction over the 8-lane group, p = exp(s) (no max shift needed),
// z[dst] += p (lane 0), agg[dst] += p*xl[src] via red.global.add.v4.f32.
__global__ void k_edge(const int* __restrict__ src, const int* __restrict__ dst,
                       const float* __restrict__ ea,
                       const float* __restrict__ We, const float* __restrict__ att,
                       float* __restrict__ agg, float* __restrict__ z,
                       int e_real, int etot) {
    int t = blockIdx.x * blockDim.x + threadIdx.x;
    int e = t >> 3;
    if (e >= etot) return;
    int sub = t & 7;

    int s_i, d_i; float a;
    if (e < e_real) { s_i = src[e]; d_i = dst[e]; a = ea[e]; }
    else            { s_i = d_i = e - e_real;     a = g_mean[e - e_real]; }

    float4 u = *(const float4*)(g_xl + s_i * F + sub * 4);
    float4 v = *(const float4*)(g_xr + d_i * F + sub * 4);
    float4 w = __ldg((const float4*)We + sub);
    float4 tt = __ldg((const float4*)att + sub);

    float acc;
    acc = lrelu(u.x + v.x + a * w.x) * tt.x;
    acc = fmaf(lrelu(u.y + v.y + a * w.y), tt.y, acc);
    acc = fmaf(lrelu(u.z + v.z + a * w.z), tt.z, acc);
    acc = fmaf(lrelu(u.w + v.w + a * w.w), tt.w, acc);

    acc += __shfl_xor_sync(0xffffffffu, acc, 4);
    acc += __shfl_xor_sync(0xffffffffu, acc, 2);
    acc += __shfl_xor_sync(0xffffffffu, acc, 1);

    float p = __expf(acc);
    if (sub == 0) atomicAdd(&z[d_i], p);

    float px = p * u.x, py = p * u.y, pz = p * u.z, pw = p * u.w;
    float* o = agg + d_i * F + sub * 4;
    asm volatile("red.global.add.v4.f32 [%0], {%1,%2,%3,%4};"
                 :: "l"(o), "f"(px), "f"(py), "f"(pz), "f"(pw) : "memory");
}

// ------------------------------- epilogues ---------------------------------

__global__ void k_epi_relu(const float* __restrict__ agg, const float* __restrict__ z,
                           const float* __restrict__ b, float* __restrict__ h, int n) {
    int i = blockIdx.x * blockDim.x + threadIdx.x;
    if (i >= n * F) return;
    h[i] = fmaxf(agg[i] / z[i >> 5] + b[i & (F - 1)], 0.0f);
}

__global__ void k_epi(float* __restrict__ out, const float* __restrict__ z,
                      const float* __restrict__ b, int n) {
    int i = blockIdx.x * blockDim.x + threadIdx.x;
    if (i >= n * F) return;
    out[i] = out[i] / z[i >> 5] + b[i & (F - 1)];
}

// ---------------------------------------------------------------------------

extern "C" void kernel_launch(void* const* d_in, const int* in_sizes, int n_in,
                              void* d_out, int out_size) {
    const float* x   = (const float*)d_in[0];
    const int*   src = (const int*)d_in[1];
    const int*   dst = (const int*)d_in[2];
    const float* ea  = (const float*)d_in[3];
    const float* Wl1 = (const float*)d_in[4];
    const float* bl1 = (const float*)d_in[5];
    const float* Wr1 = (const float*)d_in[6];
    const float* br1 = (const float*)d_in[7];
    const float* We1 = (const float*)d_in[8];
    const float* at1 = (const float*)d_in[9];
    const float* b1  = (const float*)d_in[10];
    const float* Wl2 = (const float*)d_in[11];
    const float* bl2 = (const float*)d_in[12];
    const float* Wr2 = (const float*)d_in[13];
    const float* br2 = (const float*)d_in[14];
    const float* We2 = (const float*)d_in[15];
    const float* at2 = (const float*)d_in[16];
    const float* b2  = (const float*)d_in[17];

    const int n    = in_sizes[0] / 128;   // 100000
    const int e    = in_sizes[1];         // 1600000
    const int etot = e + n;

    float* out = (float*)d_out;
    float* d_xl;   cudaGetSymbolAddress((void**)&d_xl,   g_xl);
    float* d_xr;   cudaGetSymbolAddress((void**)&d_xr,   g_xr);
    float* d_agg;  cudaGetSymbolAddress((void**)&d_agg,  g_agg);
    float* d_h;    cudaGetSymbolAddress((void**)&d_h,    g_h);
    float* d_z;    cudaGetSymbolAddress((void**)&d_z,    g_z);
    float* d_cnt;  cudaGetSymbolAddress((void**)&d_cnt,  g_cnt);
    float* d_asum; cudaGetSymbolAddress((void**)&d_asum, g_asum);

    const int T = 256;
    const int gN   = (n + T - 1) / T;
    const int gNF  = (n * F + T - 1) / T;
    const int gE   = (e + T - 1) / T;
    const int gEW  = (etot * 8 + T - 1) / T;   // 8 lanes per edge
    const int gP   = 444;                      // persistent GEMM grid (3/SM)

    const int smem128 = (2 * F * (128 + 4) + 2 * 32 * 128) * sizeof(float); // ~66.5KB
    const int smem32  = (2 * F * (32 + 4)  + 2 * 32 * 32)  * sizeof(float); // ~17.4KB
    cudaFuncSetAttribute(k_gemm_lr<128>, cudaFuncAttributeMaxDynamicSharedMemorySize, smem128);

    // Self-loop mean edge_attr (shared by both layers)
    k_zero2<<<gN, T>>>(d_cnt, d_asum, n);
    k_deg<<<gE, T>>>(dst, ea, e);
    k_mean<<<gN, T>>>(n);

    // ---------------- Layer 1 ----------------
    k_gemm_lr<128><<<gP, T, smem128>>>(x, Wl1, bl1, Wr1, br1, d_xl, d_xr, n);
    k_init<<<gNF, T>>>(d_z, d_agg, n);
    k_edge<<<gEW, T>>>(src, dst, ea, We1, at1, d_agg, d_z, e, etot);
    k_epi_relu<<<gNF, T>>>(d_agg, d_z, b1, d_h, n);

    // ---------------- Layer 2 ----------------
    k_gemm_lr<32><<<gP, T, smem32>>>(d_h, Wl2, bl2, Wr2, br2, d_xl, d_xr, n);
    k_init<<<gNF, T>>>(d_z, out, n);
    k_edge<<<gEW, T>>>(src, dst, ea, We2, at2, out, d_z, e, etot);
    k_epi<<<gNF, T>>>(out, d_z, b2, n);
}